// round 9
// baseline (speedup 1.0000x reference)
#include <cuda_runtime.h>
#include <cstdint>

#define BATCH 1024
#define TLEN  4096
#define DIN   8
#define PF    4        // prefetch depth (register pipeline)

#define NL2E  (-1.4426950408889634f)   // -log2(e)
#define P2L2E ( 2.8853900817779268f)   //  2*log2(e)

// Layer-0 input gates, [t][b] layout, float4:
//   .x = -L2E*(W_r x + b_ih_r + b_hh_r)
//   .y = -L2E*(W_z x + b_ih_z + b_hh_z)
//   .z = 2L2E*(W_n x + b_ih_n)
// Zero-padded beyond TLEN (device globals zero-init; pad never written).
__device__ float4 g_gx[(TLEN + 2 * PF) * BATCH];

__device__ __forceinline__ float fast_ex2(float x) {
    float y; asm("ex2.approx.f32 %0, %1;" : "=f"(y) : "f"(x)); return y;
}
__device__ __forceinline__ float fast_rcp(float x) {
    float y; asm("rcp.approx.f32 %0, %1;" : "=f"(y) : "f"(x)); return y;
}

// ---------------------------------------------------------------------------
// Kernel 1: precompute pre-scaled layer-0 input gates.
// ---------------------------------------------------------------------------
__global__ void gx_kernel(const float* __restrict__ x,
                          const float* __restrict__ wih0,
                          const float* __restrict__ bih0,
                          const float* __restrict__ bhh0) {
    int idx = blockIdx.x * blockDim.x + threadIdx.x;
    if (idx >= BATCH * TLEN) return;
    int t = idx >> 10;          // / BATCH
    int b = idx & (BATCH - 1);  // % BATCH

    const float4* xr = reinterpret_cast<const float4*>(x + ((size_t)b * TLEN + t) * DIN);
    float4 a0 = __ldg(xr);
    float4 a1 = __ldg(xr + 1);

    float g[3];
#pragma unroll
    for (int gi = 0; gi < 3; gi++) {
        const float* w = wih0 + gi * DIN;
        float s = __ldg(bih0 + gi);
        s = fmaf(a0.x, __ldg(w + 0), s);
        s = fmaf(a0.y, __ldg(w + 1), s);
        s = fmaf(a0.z, __ldg(w + 2), s);
        s = fmaf(a0.w, __ldg(w + 3), s);
        s = fmaf(a1.x, __ldg(w + 4), s);
        s = fmaf(a1.y, __ldg(w + 5), s);
        s = fmaf(a1.z, __ldg(w + 6), s);
        s = fmaf(a1.w, __ldg(w + 7), s);
        g[gi] = s;
    }
    g_gx[idx] = make_float4(NL2E * (g[0] + __ldg(bhh0 + 0)),
                            NL2E * (g[1] + __ldg(bhh0 + 1)),
                            P2L2E * g[2], 0.0f);
}

// ---------------------------------------------------------------------------
// Kernel 2: systolic scan. One warp per 8 batch elements; lane = layer*8+bi.
// Skew-2: at iter s, layer l processes t = s - 2l. Cross-layer handoff via a
// 2-slot smem ring: store h at end of iter s into slot s&1; the LDS for the
// NEXT iter's input (slot (s+1)&1, written at end of iter s-1) is issued
// right after — a full iteration of slack on both sides of the LDS.
// Sigmoids via ex2+rcp (MUFU), log2e pre-folded.
// ---------------------------------------------------------------------------
__global__ void __launch_bounds__(32, 1)
scan_kernel(const float* __restrict__ whh0, const float* __restrict__ bhh0,
            const float* __restrict__ wih1, const float* __restrict__ whh1,
            const float* __restrict__ bih1, const float* __restrict__ bhh1,
            const float* __restrict__ wih2, const float* __restrict__ whh2,
            const float* __restrict__ bih2, const float* __restrict__ bhh2,
            float* __restrict__ out) {
    __shared__ float hbuf_s[64];
    volatile float* hb = hbuf_s;

    int lane = threadIdx.x & 31;
    int la   = lane >> 3;                 // 0,1,2 = layer; 3 = spare lanes
    int b    = blockIdx.x * 8 + (lane & 7);
    bool l0  = (la == 0);
    int  src = (lane - 8) & 31;           // producer lane (garbage for la==0, unused)

    // zero both ring slots (single warp; no sync needed)
    hb[lane] = 0.0f;
    hb[lane + 32] = 0.0f;

    // Per-layer pointer tables (la==3 duplicates layer 2; results unused).
    const float* whh_a[4] = {whh0, whh1, whh2, whh2};
    const float* bhh_a[4] = {bhh0, bhh1, bhh2, bhh2};
    const float* wih_a[4] = {whh0, wih1, wih2, wih2};  // [0] is a dummy
    const float* bih_a[4] = {bhh0, bih1, bih2, bih2};  // [0] is a dummy

    const float* whh = whh_a[la];
    const float* bhh = bhh_a[la];
    const float* wih = wih_a[la];
    const float* bih = bih_a[la];

    // Recurrent constants (pre-scaled)
    float wrs = NL2E  * __ldg(whh + 0);
    float wzs = NL2E  * __ldg(whh + 1);
    float wn2 = P2L2E * __ldg(whh + 2);
    float cn2 = P2L2E * __ldg(bhh + 2);
    // Input-side constants: layer 0 passes g through (u=1, d=0).
    float urs = l0 ? 1.0f : NL2E  * __ldg(wih + 0);
    float uzs = l0 ? 1.0f : NL2E  * __ldg(wih + 1);
    float un2 = l0 ? 1.0f : P2L2E * __ldg(wih + 2);
    float drs = l0 ? 0.0f : NL2E  * (__ldg(bih + 0) + __ldg(bhh + 0));
    float dzs = l0 ? 0.0f : NL2E  * (__ldg(bih + 1) + __ldg(bhh + 1));
    float dn2 = l0 ? 0.0f : P2L2E * __ldg(bih + 2);

    float h = 0.0f;        // this lane's layer state
    float i_cur = 0.0f;    // input from previous layer for the CURRENT iter
    int   first_s = 2 * la;

    // ---- peel s = 0..3 (skew startup; updates predicated) ----
#pragma unroll
    for (int s = 0; s < 4; s++) {
        float4 g = g_gx[s * BATCH + b];
        float ir = l0 ? g.x : i_cur;
        float iz = l0 ? g.y : i_cur;
        float im = l0 ? g.z : i_cur;
        float yr = fmaf(h, wrs, fmaf(ir, urs, drs));
        float yz = fmaf(h, wzs, fmaf(iz, uzs, dzs));
        float r  = fast_rcp(1.0f + fast_ex2(yr));
        float z  = fast_rcp(1.0f + fast_ex2(yz));
        float yn = fmaf(r, fmaf(h, wn2, cn2), fmaf(im, un2, dn2));
        float q  = fast_rcp(1.0f + fast_ex2(yn));
        float n  = fmaf(-2.0f, q, 1.0f);
        float omz = 1.0f - z;
        float zh  = z * h;
        float hn  = fmaf(omz, n, zh);
        h = (s >= first_s) ? hn : 0.0f;
        hb[(s & 1) * 32 + lane] = h;           // publish h(s)
        i_cur = hb[((s + 1) & 1) * 32 + src];  // fetch h_prev(s-1) for iter s+1
    }

    // ---- register prefetch pipeline: rows 4..4+PF-1 ----
    float4 buf[PF];
#pragma unroll
    for (int j = 0; j < PF; j++) buf[j] = g_gx[(4 + j) * BATCH + b];

    // ---- main loop: s = 4 .. TLEN+3, branch-free (4096 iters, 1024 x PF) ----
    for (int sb = 4; sb < TLEN + 4; sb += PF) {
#pragma unroll
        for (int j = 0; j < PF; j++) {
            int s = sb + j;
            float4 g = buf[j];
            buf[j] = g_gx[(s + PF) * BATCH + b];   // zero pad keeps in-bounds

            float ir = l0 ? g.x : i_cur;
            float iz = l0 ? g.y : i_cur;
            float im = l0 ? g.z : i_cur;

            float pre_r = fmaf(ir, urs, drs);
            float pre_z = fmaf(iz, uzs, dzs);
            float pre_n = fmaf(im, un2, dn2);

            float yr = fmaf(h, wrs, pre_r);
            float yz = fmaf(h, wzs, pre_z);
            float er = fast_ex2(yr);
            float ez = fast_ex2(yz);
            float r  = fast_rcp(1.0f + er);
            float z  = fast_rcp(1.0f + ez);
            float ghn2 = fmaf(h, wn2, cn2);
            float yn = fmaf(r, ghn2, pre_n);
            float en = fast_ex2(yn);
            float q  = fast_rcp(1.0f + en);
            float n  = fmaf(-2.0f, q, 1.0f);
            float omz = 1.0f - z;                   // ready before n
            float zh  = z * h;                      // ready before n
            h = fmaf(omz, n, zh);                   // 4 cyc after n

            hb[(s & 1) * 32 + lane] = h;            // publish h(s)
            i_cur = hb[((s + 1) & 1) * 32 + src];   // h_prev(s-1), slack ~1 iter
        }
    }

    // Layer-2 lanes (16..23) hold h2 after t = TLEN-1 (processed at s=TLEN+3).
    if (la == 2) out[b] = h;
}

// ---------------------------------------------------------------------------
extern "C" void kernel_launch(void* const* d_in, const int* in_sizes, int n_in,
                              void* d_out, int out_size) {
    const float* x    = (const float*)d_in[0];
    const float* wih0 = (const float*)d_in[1];
    const float* whh0 = (const float*)d_in[2];
    const float* bih0 = (const float*)d_in[3];
    const float* bhh0 = (const float*)d_in[4];
    const float* wih1 = (const float*)d_in[5];
    const float* whh1 = (const float*)d_in[6];
    const float* bih1 = (const float*)d_in[7];
    const float* bhh1 = (const float*)d_in[8];
    const float* wih2 = (const float*)d_in[9];
    const float* whh2 = (const float*)d_in[10];
    const float* bih2 = (const float*)d_in[11];
    const float* bhh2 = (const float*)d_in[12];
    float* out = (float*)d_out;

    gx_kernel<<<(BATCH * TLEN + 255) / 256, 256>>>(x, wih0, bih0, bhh0);
    scan_kernel<<<BATCH / 8, 32>>>(whh0, bhh0,
                                   wih1, whh1, bih1, bhh1,
                                   wih2, whh2, bih2, bhh2, out);
}

// round 11
// speedup vs baseline: 1.0785x; 1.0785x over previous
#include <cuda_runtime.h>
#include <cstdint>

#define BATCH 1024
#define TLEN  4096
#define DIN   8
#define PF    4        // prefetch depth (register pipeline)

#define NL2E  (-1.4426950408889634f)   // -log2(e)
#define P2L2E ( 2.8853900817779268f)   //  2*log2(e)

// Layer-0 input gates, [t][b] layout, float4:
//   .x = -L2E*(W_r x + b_ih_r + b_hh_r)
//   .y = -L2E*(W_z x + b_ih_z + b_hh_z)
//   .z = 2L2E*(W_n x + b_ih_n)
// Zero-padded beyond TLEN by 2*PF rows (device globals zero-init; pad never
// written; max row touched = TLEN+3+PF <= TLEN+2*PF-1).
__device__ float4 g_gx[(TLEN + 2 * PF) * BATCH];

__device__ __forceinline__ float fast_ex2(float x) {
    float y; asm("ex2.approx.f32 %0, %1;" : "=f"(y) : "f"(x)); return y;
}
__device__ __forceinline__ float fast_rcp(float x) {
    float y; asm("rcp.approx.f32 %0, %1;" : "=f"(y) : "f"(x)); return y;
}

// ---------------------------------------------------------------------------
// Kernel 1: precompute pre-scaled layer-0 input gates.
// ---------------------------------------------------------------------------
__global__ void gx_kernel(const float* __restrict__ x,
                          const float* __restrict__ wih0,
                          const float* __restrict__ bih0,
                          const float* __restrict__ bhh0) {
    int idx = blockIdx.x * blockDim.x + threadIdx.x;
    if (idx >= BATCH * TLEN) return;
    int t = idx >> 10;          // / BATCH
    int b = idx & (BATCH - 1);  // % BATCH

    const float4* xr = reinterpret_cast<const float4*>(x + ((size_t)b * TLEN + t) * DIN);
    float4 a0 = __ldg(xr);
    float4 a1 = __ldg(xr + 1);

    float g[3];
#pragma unroll
    for (int gi = 0; gi < 3; gi++) {
        const float* w = wih0 + gi * DIN;
        float s = __ldg(bih0 + gi);
        s = fmaf(a0.x, __ldg(w + 0), s);
        s = fmaf(a0.y, __ldg(w + 1), s);
        s = fmaf(a0.z, __ldg(w + 2), s);
        s = fmaf(a0.w, __ldg(w + 3), s);
        s = fmaf(a1.x, __ldg(w + 4), s);
        s = fmaf(a1.y, __ldg(w + 5), s);
        s = fmaf(a1.z, __ldg(w + 6), s);
        s = fmaf(a1.w, __ldg(w + 7), s);
        g[gi] = s;
    }
    g_gx[idx] = make_float4(NL2E * (g[0] + __ldg(bhh0 + 0)),
                            NL2E * (g[1] + __ldg(bhh0 + 1)),
                            P2L2E * g[2], 0.0f);
}

// ---------------------------------------------------------------------------
// Kernel 2: systolic scan. One warp per 8 batch elements; lane = layer*8+bi.
// Skew-2: at iter s, layer l processes t = s - 2l. Cross-layer handoff via
// shfl_up(8) double-buffered one iteration ahead (SHFL source is always
// already-final, so its 26-cyc latency sits off the h->h recurrence cycle).
// Sigmoids via ex2+rcp (MUFU), log2e pre-folded. PF=4 register prefetch with
// pointer-marching addresses (immediate-offset LDG.128s).
// ---------------------------------------------------------------------------
__global__ void __launch_bounds__(32, 1)
scan_kernel(const float* __restrict__ whh0, const float* __restrict__ bhh0,
            const float* __restrict__ wih1, const float* __restrict__ whh1,
            const float* __restrict__ bih1, const float* __restrict__ bhh1,
            const float* __restrict__ wih2, const float* __restrict__ whh2,
            const float* __restrict__ bih2, const float* __restrict__ bhh2,
            float* __restrict__ out) {
    int lane = threadIdx.x & 31;
    int la   = lane >> 3;                 // 0,1,2 = layer; 3 = spare lanes
    int b    = blockIdx.x * 8 + (lane & 7);
    bool l0  = (la == 0);

    // Per-layer pointer tables (la==3 duplicates layer 2; results unused).
    const float* whh_a[4] = {whh0, whh1, whh2, whh2};
    const float* bhh_a[4] = {bhh0, bhh1, bhh2, bhh2};
    const float* wih_a[4] = {whh0, wih1, wih2, wih2};  // [0] is a dummy
    const float* bih_a[4] = {bhh0, bih1, bih2, bih2};  // [0] is a dummy

    const float* whh = whh_a[la];
    const float* bhh = bhh_a[la];
    const float* wih = wih_a[la];
    const float* bih = bih_a[la];

    // Recurrent constants (pre-scaled)
    float wrs = NL2E  * __ldg(whh + 0);
    float wzs = NL2E  * __ldg(whh + 1);
    float wn2 = P2L2E * __ldg(whh + 2);
    float cn2 = P2L2E * __ldg(bhh + 2);
    // Input-side constants: layer 0 passes g through (u=1, d=0).
    float urs = l0 ? 1.0f : NL2E  * __ldg(wih + 0);
    float uzs = l0 ? 1.0f : NL2E  * __ldg(wih + 1);
    float un2 = l0 ? 1.0f : P2L2E * __ldg(wih + 2);
    float drs = l0 ? 0.0f : NL2E  * (__ldg(bih + 0) + __ldg(bhh + 0));
    float dzs = l0 ? 0.0f : NL2E  * (__ldg(bih + 1) + __ldg(bhh + 1));
    float dn2 = l0 ? 0.0f : P2L2E * __ldg(bih + 2);

    float h = 0.0f;        // this lane's layer state
    float i_nx = 0.0f;     // shfl double-buffer: neighbor h, one iter ahead
    int   first_s = 2 * la;

    // ---- peel s = 0..3 (skew startup; updates predicated) ----
#pragma unroll
    for (int s = 0; s < 4; s++) {
        float4 g = g_gx[s * BATCH + b];
        float i = i_nx;
        i_nx = __shfl_up_sync(0xffffffffu, h, 8);
        float ir = l0 ? g.x : i;
        float iz = l0 ? g.y : i;
        float im = l0 ? g.z : i;
        float yr = fmaf(h, wrs, fmaf(ir, urs, drs));
        float yz = fmaf(h, wzs, fmaf(iz, uzs, dzs));
        float r  = fast_rcp(1.0f + fast_ex2(yr));
        float z  = fast_rcp(1.0f + fast_ex2(yz));
        float yn = fmaf(r, fmaf(h, wn2, cn2), fmaf(im, un2, dn2));
        float q  = fast_rcp(1.0f + fast_ex2(yn));
        float n  = fmaf(-2.0f, q, 1.0f);
        float omz = 1.0f - z;
        float zh  = z * h;
        float hn  = fmaf(omz, n, zh);
        h = (s >= first_s) ? hn : 0.0f;
    }

    // ---- register prefetch pipeline: rows 4..4+PF-1 ----
    const float4* ld = g_gx + (size_t)4 * BATCH + b;   // row 4, this lane's b
    float4 buf[PF];
#pragma unroll
    for (int j = 0; j < PF; j++) buf[j] = ld[(size_t)j * BATCH];
    ld += (size_t)PF * BATCH;                          // now points at row 4+PF

    // ---- main loop: s = 4 .. TLEN+3, branch-free (4096 iters, 1024 x PF) ----
    for (int sb = 4; sb < TLEN + 4; sb += PF) {
#pragma unroll
        for (int j = 0; j < PF; j++) {
            float4 g = buf[j];
            buf[j] = ld[(size_t)j * BATCH];   // immediate-offset LDG; pad covers tail

            float i = i_nx;                          // neighbor h from iter s-1
            i_nx = __shfl_up_sync(0xffffffffu, h, 8);  // source final: off-cycle

            float ir = l0 ? g.x : i;
            float iz = l0 ? g.y : i;
            float im = l0 ? g.z : i;

            float pre_r = fmaf(ir, urs, drs);
            float pre_z = fmaf(iz, uzs, dzs);
            float pre_n = fmaf(im, un2, dn2);

            float yr = fmaf(h, wrs, pre_r);
            float yz = fmaf(h, wzs, pre_z);
            float er = fast_ex2(yr);
            float ez = fast_ex2(yz);
            float r  = fast_rcp(1.0f + er);
            float z  = fast_rcp(1.0f + ez);
            float ghn2 = fmaf(h, wn2, cn2);
            float yn = fmaf(r, ghn2, pre_n);
            float en = fast_ex2(yn);
            float q  = fast_rcp(1.0f + en);
            float n  = fmaf(-2.0f, q, 1.0f);
            float omz = 1.0f - z;                    // ready before n
            float zh  = z * h;                       // ready before n
            h = fmaf(omz, n, zh);                    // 4 cyc after n
        }
        ld += (size_t)PF * BATCH;                    // single pointer bump
    }

    // Layer-2 lanes (16..23) hold h2 after t = TLEN-1 (processed at s=TLEN+3).
    if (la == 2) out[b] = h;
}

// ---------------------------------------------------------------------------
extern "C" void kernel_launch(void* const* d_in, const int* in_sizes, int n_in,
                              void* d_out, int out_size) {
    const float* x    = (const float*)d_in[0];
    const float* wih0 = (const float*)d_in[1];
    const float* whh0 = (const float*)d_in[2];
    const float* bih0 = (const float*)d_in[3];
    const float* bhh0 = (const float*)d_in[4];
    const float* wih1 = (const float*)d_in[5];
    const float* whh1 = (const float*)d_in[6];
    const float* bih1 = (const float*)d_in[7];
    const float* bhh1 = (const float*)d_in[8];
    const float* bih2v = (const float*)d_in[11];
    const float* wih2 = (const float*)d_in[9];
    const float* whh2 = (const float*)d_in[10];
    const float* bhh2 = (const float*)d_in[12];
    float* out = (float*)d_out;

    gx_kernel<<<(BATCH * TLEN + 255) / 256, 256>>>(x, wih0, bih0, bhh0);
    scan_kernel<<<BATCH / 8, 32>>>(whh0, bhh0,
                                   wih1, whh1, bih1, bhh1,
                                   wih2, whh2, bih2v, bhh2, out);
}

// round 12
// speedup vs baseline: 2.0188x; 1.8718x over previous
#include <cuda_runtime.h>
#include <cstdint>

#define BATCH 1024
#define TLEN  4096
#define DIN   8

#define NL2E  (-1.4426950408889634f)   // -log2(e)
#define P2L2E ( 2.8853900817779268f)   //  2*log2(e)

// Prefetch geometry: ring of 32 row-slots in smem, prefetch distance 28 rows,
// 1 cp.async group per 4 rows (= one outer iteration).
#define RING_ROWS 32
#define PREF_DIST 28
#define GPAD      36   // g_gx padded rows past TLEN (max prefetched row = TLEN+31)

// Layer-0 input gates, [t][b] layout, float4:
//   .x = -L2E*(W_r x + b_ih_r + b_hh_r)
//   .y = -L2E*(W_z x + b_ih_z + b_hh_z)
//   .z = 2L2E*(W_n x + b_ih_n)
// Zero-padded beyond TLEN (device globals zero-init; pad never written).
__device__ float4 g_gx[(TLEN + GPAD) * BATCH];

__device__ __forceinline__ float fast_ex2(float x) {
    float y; asm("ex2.approx.f32 %0, %1;" : "=f"(y) : "f"(x)); return y;
}
__device__ __forceinline__ float fast_rcp(float x) {
    float y; asm("rcp.approx.f32 %0, %1;" : "=f"(y) : "f"(x)); return y;
}
__device__ __forceinline__ uint32_t smem_u32(const void* p) {
    uint32_t a;
    asm("{ .reg .u64 t; cvta.to.shared.u64 t, %1; cvt.u32.u64 %0, t; }"
        : "=r"(a) : "l"(p));
    return a;
}
__device__ __forceinline__ void cp_async16(uint32_t dst, const void* src) {
    asm volatile("cp.async.cg.shared.global [%0], [%1], 16;"
                 :: "r"(dst), "l"(src));
}
#define CP_COMMIT()  asm volatile("cp.async.commit_group;")
#define CP_WAIT(N)   asm volatile("cp.async.wait_group %0;" :: "n"(N))

// ---------------------------------------------------------------------------
// Kernel 1: precompute pre-scaled layer-0 input gates.
// ---------------------------------------------------------------------------
__global__ void gx_kernel(const float* __restrict__ x,
                          const float* __restrict__ wih0,
                          const float* __restrict__ bih0,
                          const float* __restrict__ bhh0) {
    int idx = blockIdx.x * blockDim.x + threadIdx.x;
    if (idx >= BATCH * TLEN) return;
    int t = idx >> 10;          // / BATCH
    int b = idx & (BATCH - 1);  // % BATCH

    const float4* xr = reinterpret_cast<const float4*>(x + ((size_t)b * TLEN + t) * DIN);
    float4 a0 = __ldg(xr);
    float4 a1 = __ldg(xr + 1);

    float g[3];
#pragma unroll
    for (int gi = 0; gi < 3; gi++) {
        const float* w = wih0 + gi * DIN;
        float s = __ldg(bih0 + gi);
        s = fmaf(a0.x, __ldg(w + 0), s);
        s = fmaf(a0.y, __ldg(w + 1), s);
        s = fmaf(a0.z, __ldg(w + 2), s);
        s = fmaf(a0.w, __ldg(w + 3), s);
        s = fmaf(a1.x, __ldg(w + 4), s);
        s = fmaf(a1.y, __ldg(w + 5), s);
        s = fmaf(a1.z, __ldg(w + 6), s);
        s = fmaf(a1.w, __ldg(w + 7), s);
        g[gi] = s;
    }
    g_gx[idx] = make_float4(NL2E * (g[0] + __ldg(bhh0 + 0)),
                            NL2E * (g[1] + __ldg(bhh0 + 1)),
                            P2L2E * g[2], 0.0f);
}

// ---------------------------------------------------------------------------
// Kernel 2: systolic scan. One warp per 8 batch elements; lane = layer*8+bi.
// Skew-2: at iter s, layer l processes t = s - 2l.
//  - gx rows streamed via cp.async into a 32-slot smem ring, 28 rows ahead
//    (latency-proof vs ~1000-cyc DRAM misses). Every lane prefetches its own
//    16B slot -> per-lane wait_group is sufficient, no __syncwarp.
//  - LDS consumed through a 1-row register double buffer (g_nx): off-cycle.
//  - Cross-layer handoff via shfl_up(8), double-buffered (i_nx): off-cycle.
// Sigmoids via ex2+rcp (MUFU), log2e pre-folded.
// ---------------------------------------------------------------------------
__global__ void __launch_bounds__(32, 1)
scan_kernel(const float* __restrict__ whh0, const float* __restrict__ bhh0,
            const float* __restrict__ wih1, const float* __restrict__ whh1,
            const float* __restrict__ bih1, const float* __restrict__ bhh1,
            const float* __restrict__ wih2, const float* __restrict__ whh2,
            const float* __restrict__ bih2, const float* __restrict__ bhh2,
            float* __restrict__ out) {
    // Per-lane private slots: [slot][lane] float4 -> 32*32*16 = 16 KB
    __shared__ __align__(16) float4 ring[RING_ROWS][32];

    int lane = threadIdx.x & 31;
    int la   = lane >> 3;                 // 0,1,2 = layer; 3 = spare lanes
    int b    = blockIdx.x * 8 + (lane & 7);
    bool l0  = (la == 0);

    // Per-layer pointer tables (la==3 duplicates layer 2; results unused).
    const float* whh_a[4] = {whh0, whh1, whh2, whh2};
    const float* bhh_a[4] = {bhh0, bhh1, bhh2, bhh2};
    const float* wih_a[4] = {whh0, wih1, wih2, wih2};  // [0] is a dummy
    const float* bih_a[4] = {bhh0, bih1, bih2, bih2};  // [0] is a dummy

    const float* whh = whh_a[la];
    const float* bhh = bhh_a[la];
    const float* wih = wih_a[la];
    const float* bih = bih_a[la];

    // Recurrent constants (pre-scaled)
    float wrs = NL2E  * __ldg(whh + 0);
    float wzs = NL2E  * __ldg(whh + 1);
    float wn2 = P2L2E * __ldg(whh + 2);
    float cn2 = P2L2E * __ldg(bhh + 2);
    // Input-side constants: layer 0 passes g through (u=1, d=0).
    float urs = l0 ? 1.0f : NL2E  * __ldg(wih + 0);
    float uzs = l0 ? 1.0f : NL2E  * __ldg(wih + 1);
    float un2 = l0 ? 1.0f : P2L2E * __ldg(wih + 2);
    float drs = l0 ? 0.0f : NL2E  * (__ldg(bih + 0) + __ldg(bhh + 0));
    float dzs = l0 ? 0.0f : NL2E  * (__ldg(bih + 1) + __ldg(bhh + 1));
    float dn2 = l0 ? 0.0f : P2L2E * __ldg(bih + 2);

    // Source pointer for this lane's prefetch stream (column fixed, row marches)
    const char* gsrc = reinterpret_cast<const char*>(g_gx + b);  // row 0
    uint32_t ring_base = smem_u32(&ring[0][0]) + (uint32_t)lane * 16u;

    // ---- prefetch prologue: rows 4..31, 7 groups of 4 ----
#pragma unroll
    for (int k = 0; k < 7; k++) {
#pragma unroll
        for (int r = 0; r < 4; r++) {
            int row = 4 + k * 4 + r;
            cp_async16(ring_base + (uint32_t)(row & (RING_ROWS - 1)) * 512u,
                       gsrc + (size_t)row * (BATCH * 16));
        }
        CP_COMMIT();
    }

    float h = 0.0f;        // this lane's layer state
    float i_nx = 0.0f;     // shfl double-buffer: neighbor h, one iter ahead
    int   first_s = 2 * la;

    // ---- peel s = 0..3 (skew startup; updates predicated; direct gmem) ----
#pragma unroll
    for (int s = 0; s < 4; s++) {
        float4 g = g_gx[s * BATCH + b];
        float i = i_nx;
        i_nx = __shfl_up_sync(0xffffffffu, h, 8);
        float ir = l0 ? g.x : i;
        float iz = l0 ? g.y : i;
        float im = l0 ? g.z : i;
        float yr = fmaf(h, wrs, fmaf(ir, urs, drs));
        float yz = fmaf(h, wzs, fmaf(iz, uzs, dzs));
        float r  = fast_rcp(1.0f + fast_ex2(yr));
        float z  = fast_rcp(1.0f + fast_ex2(yz));
        float yn = fmaf(r, fmaf(h, wn2, cn2), fmaf(im, un2, dn2));
        float q  = fast_rcp(1.0f + fast_ex2(yn));
        float n  = fmaf(-2.0f, q, 1.0f);
        float omz = 1.0f - z;
        float zh  = z * h;
        float hn  = fmaf(omz, n, zh);
        h = (s >= first_s) ? hn : 0.0f;
    }

    // Initialize the g double-buffer with row 4 (ensure its group landed).
    CP_WAIT(6);                                // oldest group (rows 4..7) done
    float4 g_nx = ring[4 & (RING_ROWS - 1)][lane];

    // March the prefetch source to the first in-loop row (sb=4 -> row 32).
    gsrc += (size_t)(4 + PREF_DIST) * (BATCH * 16);

    // ---- main loop: s = 4 .. TLEN+3 (outer = 4 rows) ----
    for (int sb = 4; sb < TLEN + 4; sb += 4) {
        // Rows through sb+7 are complete after this (need sb+1..sb+4 for g_nx).
        CP_WAIT(5);
#pragma unroll
        for (int j = 0; j < 4; j++) {
            int s = sb + j;
            float4 g = g_nx;
            g_nx = ring[(s + 1) & (RING_ROWS - 1)][lane];  // 1-row lookahead LDS

            float i = i_nx;                            // neighbor h from iter s-1
            i_nx = __shfl_up_sync(0xffffffffu, h, 8);  // source final: off-cycle

            float ir = l0 ? g.x : i;
            float iz = l0 ? g.y : i;
            float im = l0 ? g.z : i;

            float pre_r = fmaf(ir, urs, drs);
            float pre_z = fmaf(iz, uzs, dzs);
            float pre_n = fmaf(im, un2, dn2);

            float yr = fmaf(h, wrs, pre_r);
            float yz = fmaf(h, wzs, pre_z);
            float er = fast_ex2(yr);
            float ez = fast_ex2(yz);
            float r  = fast_rcp(1.0f + er);
            float z  = fast_rcp(1.0f + ez);
            float ghn2 = fmaf(h, wn2, cn2);
            float yn = fmaf(r, ghn2, pre_n);
            float en = fast_ex2(yn);
            float q  = fast_rcp(1.0f + en);
            float n  = fmaf(-2.0f, q, 1.0f);
            float omz = 1.0f - z;                      // ready before n
            float zh  = z * h;                         // ready before n
            h = fmaf(omz, n, zh);                      // 4 cyc after n
        }
        // Issue next group: rows sb+28..sb+31 into slots (sb-4..sb-1)&31,
        // whose last reads happened in the PREVIOUS outer iteration.
        {
            uint32_t slot0 = (uint32_t)((sb + PREF_DIST) & (RING_ROWS - 1));
#pragma unroll
            for (int r = 0; r < 4; r++)
                cp_async16(ring_base + ((slot0 + r) & (RING_ROWS - 1)) * 512u,
                           gsrc + (size_t)r * (BATCH * 16));
            CP_COMMIT();
            gsrc += (size_t)4 * (BATCH * 16);
        }
    }

    // Layer-2 lanes (16..23) hold h2 after t = TLEN-1 (processed at s=TLEN+3).
    if (la == 2) out[b] = h;
}

// ---------------------------------------------------------------------------
extern "C" void kernel_launch(void* const* d_in, const int* in_sizes, int n_in,
                              void* d_out, int out_size) {
    const float* x    = (const float*)d_in[0];
    const float* wih0 = (const float*)d_in[1];
    const float* whh0 = (const float*)d_in[2];
    const float* bih0 = (const float*)d_in[3];
    const float* bhh0 = (const float*)d_in[4];
    const float* wih1 = (const float*)d_in[5];
    const float* whh1 = (const float*)d_in[6];
    const float* bih1 = (const float*)d_in[7];
    const float* bhh1 = (const float*)d_in[8];
    const float* wih2 = (const float*)d_in[9];
    const float* whh2 = (const float*)d_in[10];
    const float* bih2 = (const float*)d_in[11];
    const float* bhh2 = (const float*)d_in[12];
    float* out = (float*)d_out;

    gx_kernel<<<(BATCH * TLEN + 255) / 256, 256>>>(x, wih0, bih0, bhh0);
    scan_kernel<<<BATCH / 8, 32>>>(whh0, bhh0,
                                   wih1, whh1, bih1, bhh1,
                                   wih2, whh2, bih2, bhh2, out);
}